// round 13
// baseline (speedup 1.0000x reference)
#include <cuda_runtime.h>

#define C        128
#define NB       16
#define GROUPS   32
#define CPG      4
#define EPS      1e-5f
#define RBLOCKS  592           // resident reduce blocks (one wave)
#define TILE     1024          // rows per work-stealing tile

// Allocation-free scratch (harness forbids cudaMalloc anywhere).
__device__ float g_sum[NB][C];
__device__ float g_sq [NB][C];
__device__ int   g_seg[NB + 1];        // segment start offsets (written by reduce)
__device__ int   g_ticket;             // work-stealing tile counter

// Pure zero init (boundary search lives in reduce blocks).
__global__ void init_kernel() {
    int i = blockIdx.x * blockDim.x + threadIdx.x;
    if (i < NB * C) { (&g_sum[0][0])[i] = 0.f; (&g_sq[0][0])[i] = 0.f; }
    if (i == 0) g_ticket = 0;
}

__device__ __forceinline__ void acc1(const float4& v, float4& s, float4& q) {
    s.x += v.x; s.y += v.y; s.z += v.z; s.w += v.w;
    q.x += v.x * v.x; q.y += v.y * v.y; q.z += v.z * v.z; q.w += v.w * v.w;
}

__device__ __forceinline__ void flush_acc(int b, int lane,
                                          const float4& s, const float4& q) {
    int c0 = lane * 4;
    atomicAdd(&g_sum[b][c0 + 0], s.x);
    atomicAdd(&g_sum[b][c0 + 1], s.y);
    atomicAdd(&g_sum[b][c0 + 2], s.z);
    atomicAdd(&g_sum[b][c0 + 3], s.w);
    atomicAdd(&g_sq [b][c0 + 0], q.x);
    atomicAdd(&g_sq [b][c0 + 1], q.y);
    atomicAdd(&g_sq [b][c0 + 2], q.z);
    atomicAdd(&g_sq [b][c0 + 3], q.w);
}

// Work-stealing reduce: 592 resident blocks claim 1024-row tiles via g_ticket.
// Per tile, warp 0 resolves segment bounds locally (warp-coop lower_bound,
// validated R10/R12) and publishes the g_seg entries this tile uniquely owns:
//   t in (prev, b0] -> t0;  t in (b0, b1] -> local search;  t in (b1, NB] -> n
// (disjoint across tiles, full coverage since tiles partition [0, n)).
// Inner loop: branch-free, bid-free, 8 independent LDG.128 per warp-iteration.
// Lane l owns channels [4l, 4l+4).
__global__ void reduce_kernel(const float4* __restrict__ data,
                              const int*    __restrict__ bid,
                              int n) {
    __shared__ int sb[NB + 2];
    __shared__ int s_tile, s_b0, s_nseg;

    int tid  = threadIdx.x;
    int lane = tid & 31;
    int wwid = tid >> 5;                      // warp in block, 0..7

    while (true) {
        if (tid == 0) s_tile = atomicAdd(&g_ticket, 1);
        __syncthreads();
        int t0 = s_tile * TILE;
        if (t0 >= n) break;                   // uniform exit
        int t1 = min(n, t0 + TILE);

        if (tid < 32) {
            int b0   = bid[t0];
            int b1   = bid[t1 - 1];
            int prev = (t0 == 0) ? -1 : bid[t0 - 1];
            if (lane == 0) {
                s_b0   = b0;
                s_nseg = b1 - b0 + 1;
                sb[0]  = t0;
                sb[b1 - b0 + 1] = t1;
            }
            for (int t = prev + 1 + lane; t <= b0; t += 32) g_seg[t] = t0;
            if (t1 == n)
                for (int t = b1 + 1 + lane; t <= NB; t += 32) g_seg[t] = n;
            for (int t = b0 + 1; t <= b1; ++t) {
                int lo = t0, hi = t1;
                while (hi - lo > 32) {
                    int step = (hi - lo) / 33 + 1;
                    int p    = lo + (lane + 1) * step;
                    bool pred = (p < hi) && (bid[p] < t);
                    int cnt = __popc(__ballot_sync(0xffffffffu, pred));
                    int lo0 = lo;
                    lo = lo0 + cnt * step;
                    hi = min(hi, lo0 + (cnt + 1) * step + 1);
                }
                int i = lo + lane;
                bool pred = (i < hi) && (bid[i] < t);
                int ans = lo + __popc(__ballot_sync(0xffffffffu, pred));
                if (lane == 0) { sb[t - b0] = ans; g_seg[t] = ans; }
            }
        }
        __syncthreads();

        int b0   = s_b0;
        int nseg = s_nseg;

#pragma unroll 1
        for (int k = 0; k < nseg; ++k) {
            int b  = b0 + k;
            int rs = sb[k];
            int re = sb[k + 1];
            if (rs >= re) continue;

            float4 s = make_float4(0.f, 0.f, 0.f, 0.f);
            float4 q = make_float4(0.f, 0.f, 0.f, 0.f);

            int r = rs + wwid;
            for (; r + 56 < re; r += 64) {
                float4 v0 = __ldcs(&data[(r     ) * 32 + lane]);
                float4 v1 = __ldcs(&data[(r +  8) * 32 + lane]);
                float4 v2 = __ldcs(&data[(r + 16) * 32 + lane]);
                float4 v3 = __ldcs(&data[(r + 24) * 32 + lane]);
                float4 v4 = __ldcs(&data[(r + 32) * 32 + lane]);
                float4 v5 = __ldcs(&data[(r + 40) * 32 + lane]);
                float4 v6 = __ldcs(&data[(r + 48) * 32 + lane]);
                float4 v7 = __ldcs(&data[(r + 56) * 32 + lane]);
                acc1(v0, s, q); acc1(v1, s, q); acc1(v2, s, q); acc1(v3, s, q);
                acc1(v4, s, q); acc1(v5, s, q); acc1(v6, s, q); acc1(v7, s, q);
            }
            for (; r < re; r += 8) {
                float4 v = __ldcs(&data[r * 32 + lane]);
                acc1(v, s, q);
            }
            flush_acc(b, lane, s, q);
        }
        __syncthreads();                      // protect sb/s_tile before next claim
    }
}

// Apply with fused stats prologue (proven 81%-of-HBM shape — unchanged).
// Reference math:
//   inv_count = 1/(cnt*CPG + EPS)
//   m_g   = (sum of 4 per-channel sums) * inv_count
//   var_g = (sq_g - 2*m_g*s_g + CPG*cnt*m_g^2) * inv_count
// Lane l covers channels [4l,4l+4) == exactly group l (CPG=4, GROUPS=32).
__global__ void apply_kernel(const float4* __restrict__ data,
                             const float4* __restrict__ w4,
                             const float4* __restrict__ bias4,
                             const int*    __restrict__ bid,
                             float4*       __restrict__ out,
                             int n) {
    __shared__ float2 sms[NB][GROUPS];        // 4 KB

    int tid = threadIdx.x;
    for (int idx = tid; idx < NB * GROUPS; idx += blockDim.x) {
        int b = idx >> 5;
        int g = idx & 31;
        float cnt  = (float)(g_seg[b + 1] - g_seg[b]);
        float invc = 1.f / (cnt * (float)CPG + EPS);
        float s = 0.f, sq = 0.f;
#pragma unroll
        for (int k = 0; k < CPG; ++k) {
            s  += g_sum[b][g * 4 + k];
            sq += g_sq [b][g * 4 + k];
        }
        float m   = s * invc;
        float var = (sq - 2.f * m * s + (float)CPG * cnt * m * m) * invc;
        sms[b][g] = make_float2(m, rsqrtf(var + EPS));
    }
    __syncthreads();

    int lane   = tid & 31;
    int warp   = (blockIdx.x * blockDim.x + tid) >> 5;
    int nwarps = (gridDim.x * blockDim.x) >> 5;
    float4 w  = w4[lane];
    float4 bb = bias4[lane];

    for (int r = warp; r < n; r += nwarps) {
        int b = bid[r];                       // warp-uniform
        float2 ms = sms[b][lane];             // smem broadcast
        float4 v  = __ldcs(&data[r * 32 + lane]);
        float4 o;
        o.x = (v.x - ms.x) * ms.y * w.x + bb.x;
        o.y = (v.y - ms.x) * ms.y * w.y + bb.y;
        o.z = (v.z - ms.x) * ms.y * w.z + bb.z;
        o.w = (v.w - ms.x) * ms.y * w.w + bb.w;
        __stcs(&out[r * 32 + lane], o);
    }
}

extern "C" void kernel_launch(void* const* d_in, const int* in_sizes, int n_in,
                              void* d_out, int out_size) {
    const float* data = (const float*)d_in[0];
    const float* w    = (const float*)d_in[1];
    const float* bias = (const float*)d_in[2];
    const int*   bid  = (const int*)d_in[3];
    int n = in_sizes[3];                      // rows (batch_id length)

    init_kernel<<<16, 128>>>();               // pure zero + ticket reset

    reduce_kernel<<<RBLOCKS, 256>>>((const float4*)data, bid, n);

    apply_kernel<<<2048, 256>>>((const float4*)data, (const float4*)w,
                                (const float4*)bias, bid,
                                (float4*)d_out, n);
}

// round 14
// speedup vs baseline: 1.1306x; 1.1306x over previous
#include <cuda_runtime.h>

#define C        128
#define NB       16
#define GROUPS   32
#define CPG      4
#define EPS      1e-5f
#define RBLOCKS  592           // reduce blocks (4/SM, one wave), contiguous chunks

// Allocation-free scratch (harness forbids cudaMalloc anywhere).
// Statically zero-initialized; reduce's epilogue re-zeroes for the next replay.
__device__ float g_sum[NB][C];
__device__ float g_sq [NB][C];
__device__ int   g_seg[NB + 1];        // segment start offsets (written by reduce)
__device__ int   g_ready;              // zeroing-done flag (posts to 16)
__device__ int   g_done;               // block completion counter (resets flags)

__device__ __forceinline__ void acc1(const float4& v, float4& s, float4& q) {
    s.x += v.x; s.y += v.y; s.z += v.z; s.w += v.w;
    q.x += v.x * v.x; q.y += v.y * v.y; q.z += v.z * v.z; q.w += v.w * v.w;
}

__device__ __forceinline__ void flush_acc(int b, int lane,
                                          const float4& s, const float4& q) {
    int c0 = lane * 4;
    atomicAdd(&g_sum[b][c0 + 0], s.x);
    atomicAdd(&g_sum[b][c0 + 1], s.y);
    atomicAdd(&g_sum[b][c0 + 2], s.z);
    atomicAdd(&g_sum[b][c0 + 3], s.w);
    atomicAdd(&g_sq [b][c0 + 0], q.x);
    atomicAdd(&g_sq [b][c0 + 1], q.y);
    atomicAdd(&g_sq [b][c0 + 2], q.z);
    atomicAdd(&g_sq [b][c0 + 3], q.w);
}

__device__ __forceinline__ void finish_block() {
    // Last block to finish resets the flags for the next graph replay.
    __syncthreads();
    if (threadIdx.x == 0) {
        __threadfence();
        int d = atomicAdd(&g_done, 1);
        if (d == RBLOCKS - 1) { g_ready = 0; g_done = 0; }
    }
}

// Block owns contiguous rows [r0, r1). Blocks 0..15 first zero their accumulator
// slice and post g_ready (no init kernel). Warp 0 resolves this block's segment
// boundaries locally (warp-coop lower_bound, validated R10/R12) and publishes
// the g_seg entries it uniquely owns:
//   t in (prev, b0] -> r0;  t in (b0, b1] -> local search;  t in (b1, NB] -> n
// (disjoint across blocks, covering 0..NB). The g_ready spin sits AFTER the
// ~170us streaming phase, so its wait is ~zero and the steady-state loop stays
// barrier-free (R13 lesson). Inner loop: branch-free, bid-free, 8 independent
// LDG.128 per warp-iteration. Lane l owns channels [4l, 4l+4).
__global__ void reduce_kernel(const float4* __restrict__ data,
                              const int*    __restrict__ bid,
                              int n, int chunk) {
    __shared__ int sb[NB + 2];               // local segment bounds
    __shared__ int s_b0, s_nseg;

    int tid  = threadIdx.x;
    int lane = tid & 31;
    int wwid = tid >> 5;                      // warp in block, 0..7

    // Inline zeroing (replaces init_kernel): block b zeroes g_sum[b]/g_sq[b].
    if (blockIdx.x < NB) {
        if (tid < C) {
            g_sum[blockIdx.x][tid] = 0.f;
            g_sq [blockIdx.x][tid] = 0.f;
        }
        __syncthreads();
        if (tid == 0) {
            __threadfence();
            atomicAdd(&g_ready, 1);
        }
    }

    int r0 = blockIdx.x * chunk;
    if (r0 >= n) { finish_block(); return; }
    int r1 = min(n, r0 + chunk);

    if (tid < 32) {
        int b0   = bid[r0];
        int b1   = bid[r1 - 1];
        int prev = (r0 == 0) ? -1 : bid[r0 - 1];
        if (lane == 0) {
            s_b0   = b0;
            s_nseg = b1 - b0 + 1;
            sb[0]  = r0;
            sb[b1 - b0 + 1] = r1;
        }
        for (int t = prev + 1 + lane; t <= b0; t += 32) g_seg[t] = r0;
        if (r1 == n)
            for (int t = b1 + 1 + lane; t <= NB; t += 32) g_seg[t] = n;
        for (int t = b0 + 1; t <= b1; ++t) {
            int lo = r0, hi = r1;
            while (hi - lo > 32) {
                int step = (hi - lo) / 33 + 1;
                int p    = lo + (lane + 1) * step;
                bool pred = (p < hi) && (bid[p] < t);
                int cnt = __popc(__ballot_sync(0xffffffffu, pred));
                int lo0 = lo;
                lo = lo0 + cnt * step;
                hi = min(hi, lo0 + (cnt + 1) * step + 1);
            }
            int i = lo + lane;
            bool pred = (i < hi) && (bid[i] < t);
            int ans = lo + __popc(__ballot_sync(0xffffffffu, pred));
            if (lane == 0) { sb[t - b0] = ans; g_seg[t] = ans; }
        }
    }
    __syncthreads();

    int b0   = s_b0;
    int nseg = s_nseg;

    // Accumulate all segments first (register partials), flush after the spin.
    float4 sa[2], qa[2];                      // nseg is 1 for 577+ of 592 blocks
#pragma unroll 1
    for (int k = 0; k < nseg; ++k) {
        int rs = sb[k];
        int re = sb[k + 1];

        float4 s = make_float4(0.f, 0.f, 0.f, 0.f);
        float4 q = make_float4(0.f, 0.f, 0.f, 0.f);

        int r = rs + wwid;
        for (; r + 56 < re; r += 64) {
            float4 v0 = __ldcs(&data[(r     ) * 32 + lane]);
            float4 v1 = __ldcs(&data[(r +  8) * 32 + lane]);
            float4 v2 = __ldcs(&data[(r + 16) * 32 + lane]);
            float4 v3 = __ldcs(&data[(r + 24) * 32 + lane]);
            float4 v4 = __ldcs(&data[(r + 32) * 32 + lane]);
            float4 v5 = __ldcs(&data[(r + 40) * 32 + lane]);
            float4 v6 = __ldcs(&data[(r + 48) * 32 + lane]);
            float4 v7 = __ldcs(&data[(r + 56) * 32 + lane]);
            acc1(v0, s, q); acc1(v1, s, q); acc1(v2, s, q); acc1(v3, s, q);
            acc1(v4, s, q); acc1(v5, s, q); acc1(v6, s, q); acc1(v7, s, q);
        }
        for (; r < re; r += 8) {
            float4 v = __ldcs(&data[r * 32 + lane]);
            acc1(v, s, q);
        }
        if (k < 2) { sa[k] = s; qa[k] = q; }
        else {      // nseg > 2 is possible only if a chunk spans >2 segments
            // spin then flush directly (rare path, at most a handful of blocks)
            if (tid == 0) while (*(volatile int*)&g_ready < NB) {}
            __syncthreads();
            __threadfence();
            flush_acc(b0 + k, lane, s, q);
        }
    }

    // Zeroing finished ~170us ago; this spin is effectively free.
    if (tid == 0) while (*(volatile int*)&g_ready < NB) {}
    __syncthreads();
    __threadfence();

#pragma unroll
    for (int k = 0; k < 2; ++k)
        if (k < nseg) {
            int rs = sb[k], re = sb[k + 1];
            if (rs < re) flush_acc(b0 + k, lane, sa[k], qa[k]);
        }

    finish_block();
}

// Apply with fused stats prologue (proven 81%-of-HBM shape — unchanged).
// Reference math:
//   inv_count = 1/(cnt*CPG + EPS)
//   m_g   = (sum of 4 per-channel sums) * inv_count
//   var_g = (sq_g - 2*m_g*s_g + CPG*cnt*m_g^2) * inv_count
// Lane l covers channels [4l,4l+4) == exactly group l (CPG=4, GROUPS=32).
__global__ void apply_kernel(const float4* __restrict__ data,
                             const float4* __restrict__ w4,
                             const float4* __restrict__ bias4,
                             const int*    __restrict__ bid,
                             float4*       __restrict__ out,
                             int n) {
    __shared__ float2 sms[NB][GROUPS];        // 4 KB

    int tid = threadIdx.x;
    for (int idx = tid; idx < NB * GROUPS; idx += blockDim.x) {
        int b = idx >> 5;
        int g = idx & 31;
        float cnt  = (float)(g_seg[b + 1] - g_seg[b]);
        float invc = 1.f / (cnt * (float)CPG + EPS);
        float s = 0.f, sq = 0.f;
#pragma unroll
        for (int k = 0; k < CPG; ++k) {
            s  += g_sum[b][g * 4 + k];
            sq += g_sq [b][g * 4 + k];
        }
        float m   = s * invc;
        float var = (sq - 2.f * m * s + (float)CPG * cnt * m * m) * invc;
        sms[b][g] = make_float2(m, rsqrtf(var + EPS));
    }
    __syncthreads();

    int lane   = tid & 31;
    int warp   = (blockIdx.x * blockDim.x + tid) >> 5;
    int nwarps = (gridDim.x * blockDim.x) >> 5;
    float4 w  = w4[lane];
    float4 bb = bias4[lane];

    for (int r = warp; r < n; r += nwarps) {
        int b = bid[r];                       // warp-uniform
        float2 ms = sms[b][lane];             // smem broadcast
        float4 v  = __ldcs(&data[r * 32 + lane]);
        float4 o;
        o.x = (v.x - ms.x) * ms.y * w.x + bb.x;
        o.y = (v.y - ms.x) * ms.y * w.y + bb.y;
        o.z = (v.z - ms.x) * ms.y * w.z + bb.z;
        o.w = (v.w - ms.x) * ms.y * w.w + bb.w;
        __stcs(&out[r * 32 + lane], o);
    }
}

extern "C" void kernel_launch(void* const* d_in, const int* in_sizes, int n_in,
                              void* d_out, int out_size) {
    const float* data = (const float*)d_in[0];
    const float* w    = (const float*)d_in[1];
    const float* bias = (const float*)d_in[2];
    const int*   bid  = (const int*)d_in[3];
    int n = in_sizes[3];                      // rows (batch_id length)

    int chunk = (n + RBLOCKS - 1) / RBLOCKS;  // contiguous rows per block
    reduce_kernel<<<RBLOCKS, 256>>>((const float4*)data, bid, n, chunk);

    apply_kernel<<<2048, 256>>>((const float4*)data, (const float4*)w,
                                (const float4*)bias, bid,
                                (float4*)d_out, n);
}

// round 15
// speedup vs baseline: 1.1921x; 1.0544x over previous
#include <cuda_runtime.h>

#define C        128
#define NB       16
#define GROUPS   32
#define CPG      4
#define EPS      1e-5f
#define RBLOCKS  592           // reduce blocks (4/SM, one wave), contiguous chunks

// Allocation-free scratch (harness forbids cudaMalloc anywhere).
__device__ float g_sum[NB][C];
__device__ float g_sq [NB][C];
__device__ int   g_seg[NB + 1];        // segment start offsets (written by reduce)

// Pure zero init (boundary search lives in reduce blocks).
__global__ void init_kernel() {
    int i = blockIdx.x * blockDim.x + threadIdx.x;
    if (i < NB * C) { (&g_sum[0][0])[i] = 0.f; (&g_sq[0][0])[i] = 0.f; }
}

__device__ __forceinline__ void acc1(const float4& v, float4& s, float4& q) {
    s.x += v.x; s.y += v.y; s.z += v.z; s.w += v.w;
    q.x += v.x * v.x; q.y += v.y * v.y; q.z += v.z * v.z; q.w += v.w * v.w;
}

__device__ __forceinline__ void flush_acc(int b, int lane,
                                          const float4& s, const float4& q) {
    int c0 = lane * 4;
    atomicAdd(&g_sum[b][c0 + 0], s.x);
    atomicAdd(&g_sum[b][c0 + 1], s.y);
    atomicAdd(&g_sum[b][c0 + 2], s.z);
    atomicAdd(&g_sum[b][c0 + 3], s.w);
    atomicAdd(&g_sq [b][c0 + 0], q.x);
    atomicAdd(&g_sq [b][c0 + 1], q.y);
    atomicAdd(&g_sq [b][c0 + 2], q.z);
    atomicAdd(&g_sq [b][c0 + 3], q.w);
}

// Block owns contiguous rows [r0, r1). Warp 0 resolves the block's segment
// boundaries locally (warp-cooperative lower_bound, validated R10/R12) and
// publishes the g_seg entries it uniquely owns:
//   t in (prev, b0] -> r0;  t in (b0, b1] -> local search;  t in (b1, NB] -> n
// (disjoint across blocks, covering 0..NB). Inner loop: branch-free, bid-free,
// 8 independent LDG.128 per warp-iteration (4 KB in flight per warp).
// Lane l owns channels [4l, 4l+4).
__global__ void reduce_kernel(const float4* __restrict__ data,
                              const int*    __restrict__ bid,
                              int n, int chunk) {
    __shared__ int sb[NB + 2];               // local segment bounds
    __shared__ int s_b0, s_nseg;

    int r0 = blockIdx.x * chunk;
    if (r0 >= n) return;
    int r1 = min(n, r0 + chunk);

    int tid  = threadIdx.x;
    int lane = tid & 31;
    int wwid = tid >> 5;                      // warp in block, 0..7

    if (tid < 32) {
        int b0   = bid[r0];
        int b1   = bid[r1 - 1];
        int prev = (r0 == 0) ? -1 : bid[r0 - 1];
        if (lane == 0) {
            s_b0   = b0;
            s_nseg = b1 - b0 + 1;
            sb[0]  = r0;
            sb[b1 - b0 + 1] = r1;
        }
        for (int t = prev + 1 + lane; t <= b0; t += 32) g_seg[t] = r0;
        if (r1 == n)
            for (int t = b1 + 1 + lane; t <= NB; t += 32) g_seg[t] = n;
        for (int t = b0 + 1; t <= b1; ++t) {
            int lo = r0, hi = r1;
            while (hi - lo > 32) {
                int step = (hi - lo) / 33 + 1;
                int p    = lo + (lane + 1) * step;
                bool pred = (p < hi) && (bid[p] < t);
                int cnt = __popc(__ballot_sync(0xffffffffu, pred));
                int lo0 = lo;
                lo = lo0 + cnt * step;
                hi = min(hi, lo0 + (cnt + 1) * step + 1);
            }
            int i = lo + lane;
            bool pred = (i < hi) && (bid[i] < t);
            int ans = lo + __popc(__ballot_sync(0xffffffffu, pred));
            if (lane == 0) { sb[t - b0] = ans; g_seg[t] = ans; }
        }
    }
    __syncthreads();

    int b0   = s_b0;
    int nseg = s_nseg;

#pragma unroll 1
    for (int k = 0; k < nseg; ++k) {
        int b  = b0 + k;
        int rs = sb[k];
        int re = sb[k + 1];
        if (rs >= re) continue;

        float4 s = make_float4(0.f, 0.f, 0.f, 0.f);
        float4 q = make_float4(0.f, 0.f, 0.f, 0.f);

        int r = rs + wwid;
        for (; r + 56 < re; r += 64) {
            float4 v0 = __ldcs(&data[(r     ) * 32 + lane]);
            float4 v1 = __ldcs(&data[(r +  8) * 32 + lane]);
            float4 v2 = __ldcs(&data[(r + 16) * 32 + lane]);
            float4 v3 = __ldcs(&data[(r + 24) * 32 + lane]);
            float4 v4 = __ldcs(&data[(r + 32) * 32 + lane]);
            float4 v5 = __ldcs(&data[(r + 40) * 32 + lane]);
            float4 v6 = __ldcs(&data[(r + 48) * 32 + lane]);
            float4 v7 = __ldcs(&data[(r + 56) * 32 + lane]);
            acc1(v0, s, q); acc1(v1, s, q); acc1(v2, s, q); acc1(v3, s, q);
            acc1(v4, s, q); acc1(v5, s, q); acc1(v6, s, q); acc1(v7, s, q);
        }
        for (; r < re; r += 8) {
            float4 v = __ldcs(&data[r * 32 + lane]);
            acc1(v, s, q);
        }
        flush_acc(b, lane, s, q);
    }
}

// Apply, now BID-FREE: each warp's r is monotone (stride nwarps), so its
// segment index advances via a warp-uniform walk over the 17-entry smem
// boundary table — no per-row bid load, no dependent-load chain, 8 MB less
// traffic. Stats prologue identical to R12:
//   inv_count = 1/(cnt*CPG + EPS)
//   m_g   = (sum of 4 per-channel sums) * inv_count
//   var_g = (sq_g - 2*m_g*s_g + CPG*cnt*m_g^2) * inv_count
// Lane l covers channels [4l,4l+4) == exactly group l (CPG=4, GROUPS=32).
__global__ void apply_kernel(const float4* __restrict__ data,
                             const float4* __restrict__ w4,
                             const float4* __restrict__ bias4,
                             float4*       __restrict__ out,
                             int n) {
    __shared__ float2 sms[NB][GROUPS];        // 4 KB
    __shared__ int    sseg[NB + 1];

    int tid = threadIdx.x;
    if (tid <= NB) sseg[tid] = g_seg[tid];
    for (int idx = tid; idx < NB * GROUPS; idx += blockDim.x) {
        int b = idx >> 5;
        int g = idx & 31;
        float cnt  = (float)(g_seg[b + 1] - g_seg[b]);
        float invc = 1.f / (cnt * (float)CPG + EPS);
        float s = 0.f, sq = 0.f;
#pragma unroll
        for (int k = 0; k < CPG; ++k) {
            s  += g_sum[b][g * 4 + k];
            sq += g_sq [b][g * 4 + k];
        }
        float m   = s * invc;
        float var = (sq - 2.f * m * s + (float)CPG * cnt * m * m) * invc;
        sms[b][g] = make_float2(m, rsqrtf(var + EPS));
    }
    __syncthreads();

    int lane   = tid & 31;
    int warp   = (blockIdx.x * blockDim.x + tid) >> 5;
    int nwarps = (gridDim.x * blockDim.x) >> 5;
    float4 w  = w4[lane];
    float4 bb = bias4[lane];

    int sidx = 0;                             // current segment (warp-uniform)
    for (int r = warp; r < n; r += nwarps) {
        while (r >= sseg[sidx + 1]) ++sidx;   // typically 0-1 iterations
        float2 ms = sms[sidx][lane];          // smem broadcast
        float4 v  = __ldcs(&data[r * 32 + lane]);
        float4 o;
        o.x = (v.x - ms.x) * ms.y * w.x + bb.x;
        o.y = (v.y - ms.x) * ms.y * w.y + bb.y;
        o.z = (v.z - ms.x) * ms.y * w.z + bb.z;
        o.w = (v.w - ms.x) * ms.y * w.w + bb.w;
        __stcs(&out[r * 32 + lane], o);
    }
}

extern "C" void kernel_launch(void* const* d_in, const int* in_sizes, int n_in,
                              void* d_out, int out_size) {
    const float* data = (const float*)d_in[0];
    const float* w    = (const float*)d_in[1];
    const float* bias = (const float*)d_in[2];
    const int*   bid  = (const int*)d_in[3];
    int n = in_sizes[3];                      // rows (batch_id length)

    init_kernel<<<16, 128>>>();               // pure zero, ~4us

    int chunk = (n + RBLOCKS - 1) / RBLOCKS;  // contiguous rows per block
    reduce_kernel<<<RBLOCKS, 256>>>((const float4*)data, bid, n, chunk);

    apply_kernel<<<2048, 256>>>((const float4*)data, (const float4*)w,
                                (const float4*)bias,
                                (float4*)d_out, n);
}